// round 3
// baseline (speedup 1.0000x reference)
#include <cuda_runtime.h>
#include <cuda_bf16.h>
#include <cstdint>
#include <cstddef>

// ============================================================================
// out = clip(x @ sign(W1)^T + b1, -1, 1) @ W2^T + b2
// Plain sm_100 target: legacy mma.sync (HMMA) bf16 path, cp.async + ldmatrix.
// x split hi/lo bf16 (sign weights exact in bf16); both halves accumulate into
// the same f32 MMA fragments. Layer 2 fused in epilogue, deterministic reduce.
// ============================================================================

#define BATCH   8192
#define IN_F    784
#define HID     4096
#define OUT_F   10
#define KP      832            // 784 padded to 13*64
#define NCHUNK  13
#define TILE_M  128
#define TILE_N  256
#define NT_M    (BATCH / TILE_M)   // 64
#define NT_N    (HID / TILE_N)     // 16

// ---------------- device scratch (single array; 32-bit offsets) -------------
#define AHI_OFF 0
#define ALO_OFF (BATCH * KP)               // 6,815,744
#define WB_OFF  (2 * BATCH * KP)           // 13,631,488
__device__ __nv_bfloat16 g_data[2 * BATCH * KP + HID * KP];
__device__ float g_part[(size_t)NT_N * BATCH * 16];

// ---------------- SMEM layout ------------------------------------------------
#define SM_B1    0                          // 256 f32
#define SM_W2    1024                       // 10*256 f32 = 10KB
#define SM_STG   12288                      // 3 stages x 64KB
#define STG_BYTES 65536
#define ST_AHI   0
#define ST_ALO   16384
#define ST_B     32768
#define SM_H     (SM_STG + STG_BYTES)       // h tile reuses stages 1+2
#define H_STRIDE 258                        // f32, pad for banks
#define SMEM_TOTAL (SM_H + TILE_M * H_STRIDE * 4)   // 209920
static_assert(SMEM_TOTAL <= 227 * 1024, "smem");

// ---------------- PTX helpers ------------------------------------------------
__device__ __forceinline__ uint32_t smem_u32(const void* p) {
    uint32_t a;
    asm("{ .reg .u64 t; cvta.to.shared.u64 t, %1; cvt.u32.u64 %0, t; }"
        : "=r"(a) : "l"(p));
    return a;
}
__device__ __forceinline__ void cp_async16(uint32_t sm, const void* gp) {
    asm volatile("cp.async.cg.shared.global [%0], [%1], 16;" :: "r"(sm), "l"(gp));
}
__device__ __forceinline__ void ldsm_x4(uint32_t& r0, uint32_t& r1,
                                        uint32_t& r2, uint32_t& r3, uint32_t a) {
    asm volatile("ldmatrix.sync.aligned.m8n8.x4.shared.b16 {%0,%1,%2,%3}, [%4];"
                 : "=r"(r0), "=r"(r1), "=r"(r2), "=r"(r3) : "r"(a));
}
__device__ __forceinline__ void mma_bf16(float& c0, float& c1, float& c2, float& c3,
                                         uint32_t a0, uint32_t a1, uint32_t a2,
                                         uint32_t a3, uint32_t b0, uint32_t b1) {
    asm volatile(
        "mma.sync.aligned.m16n8k16.row.col.f32.bf16.bf16.f32 "
        "{%0,%1,%2,%3}, {%4,%5,%6,%7}, {%8,%9}, {%0,%1,%2,%3};"
        : "+f"(c0), "+f"(c1), "+f"(c2), "+f"(c3)
        : "r"(a0), "r"(a1), "r"(a2), "r"(a3), "r"(b0), "r"(b1));
}

// ---------------- prep kernels ----------------------------------------------
__global__ void prep_x(const float* __restrict__ x) {
    int idx = blockIdx.x * blockDim.x + threadIdx.x;
    if (idx >= BATCH * KP) return;
    int r = idx / KP, c = idx - r * KP;
    float v = (c < IN_F) ? x[r * IN_F + c] : 0.f;
    __nv_bfloat16 hi = __float2bfloat16(v);
    g_data[AHI_OFF + idx] = hi;
    g_data[ALO_OFF + idx] = __float2bfloat16(v - __bfloat162float(hi));
}

__global__ void prep_w(const float* __restrict__ W1) {
    int idx = blockIdx.x * blockDim.x + threadIdx.x;
    if (idx >= HID * KP) return;
    int r = idx / KP, c = idx - r * KP;
    float s = 0.f;
    if (c < IN_F) {
        float v = W1[r * IN_F + c];
        s = (v > 0.f) ? 1.f : ((v < 0.f) ? -1.f : 0.f);
    }
    g_data[WB_OFF + idx] = __float2bfloat16(s);
}

__global__ void reduce_out(const float* __restrict__ b2, float* __restrict__ out) {
    int idx = blockIdx.x * blockDim.x + threadIdx.x;
    if (idx >= BATCH * OUT_F) return;
    int r = idx / OUT_F, o = idx - r * OUT_F;
    float acc = b2[o];
#pragma unroll
    for (int nt = 0; nt < NT_N; nt++)
        acc += g_part[((size_t)nt * BATCH + r) * 16 + o];
    out[idx] = acc;
}

// ---------------- main fused kernel ------------------------------------------
__global__ void __launch_bounds__(512, 1)
mlp_kernel(const float* __restrict__ b1, const float* __restrict__ W2) {
    extern __shared__ __align__(128) char smem[];
    const uint32_t sb = smem_u32(smem);
    const int tid = threadIdx.x;
    const int lane = tid & 31, wid = tid >> 5;
    const int m0 = blockIdx.x * TILE_M;
    const int n0 = blockIdx.y * TILE_N;
    const int warpM = wid & 1;        // 2 along M
    const int warpN = wid >> 1;       // 8 along N

    // preload b1 slice + W2 slice (f32)
    if (tid < 256) ((float*)(smem + SM_B1))[tid] = b1[n0 + tid];
#pragma unroll
    for (int i = tid; i < 10 * 256; i += 512)
        ((float*)(smem + SM_W2))[i] = W2[(i >> 8) * HID + n0 + (i & 255)];

    // per-thread cp.async segment offsets (16B each; 8 per thread, 4096 total)
    uint32_t goff[8], soff[8];
#pragma unroll
    for (int i = 0; i < 8; i++) {
        int idx = tid + i * 512;
        int r, seg; uint32_t gb, sbs;
        if (idx < 1024)      { r = idx >> 3;              seg = idx & 7;
                               gb = (uint32_t)(AHI_OFF + (m0 + r) * KP) * 2; sbs = ST_AHI; }
        else if (idx < 2048) { int li = idx - 1024; r = li >> 3; seg = li & 7;
                               gb = (uint32_t)(ALO_OFF + (m0 + r) * KP) * 2; sbs = ST_ALO; }
        else                 { int li = idx - 2048; r = li >> 3; seg = li & 7;
                               gb = (uint32_t)(WB_OFF + (n0 + r) * KP) * 2;  sbs = ST_B; }
        goff[i] = gb + seg * 16;
        soff[i] = sbs + r * 128 + ((seg ^ (r & 7)) * 16);
    }
    const char* gB = (const char*)g_data;

    // prologue: fill stages 0..2 (chunks 0..2)
#pragma unroll
    for (int pc = 0; pc < 3; pc++) {
        uint32_t st = sb + SM_STG + pc * STG_BYTES;
#pragma unroll
        for (int i = 0; i < 8; i++)
            cp_async16(st + soff[i], gB + goff[i] + pc * 128);
        asm volatile("cp.async.commit_group;");
    }

    // ldmatrix per-thread invariants
    const int rA  = warpM * 64 + (lane & 15);            // A row base (mf*16 added)
    const int sxA = rA & 7;
    const int kaA = lane >> 4;                           // k8-half select
    const int rB  = warpN * 32 + ((lane >> 4) << 3) + (lane & 7);
    const int sxB = rB & 7;
    const int kbB = (lane >> 3) & 1;

    float c[4][4][4];
#pragma unroll
    for (int mf = 0; mf < 4; mf++)
#pragma unroll
        for (int nf = 0; nf < 4; nf++)
#pragma unroll
            for (int q = 0; q < 4; q++) c[mf][nf][q] = 0.f;

    int stg_i = 0;
#pragma unroll 1
    for (int ck = 0; ck < NCHUNK; ck++) {
        asm volatile("cp.async.wait_group 2;");
        __syncthreads();
        const uint32_t stg = sb + SM_STG + stg_i * STG_BYTES;

#pragma unroll
        for (int ks = 0; ks < 4; ks++) {
            uint32_t b[4][2];
#pragma unroll
            for (int nfp = 0; nfp < 2; nfp++) {
                uint32_t addr = stg + ST_B + (uint32_t)(rB + nfp * 16) * 128
                              + (uint32_t)(((ks * 2 + kbB) ^ sxB) * 16);
                ldsm_x4(b[2 * nfp][0], b[2 * nfp][1],
                        b[2 * nfp + 1][0], b[2 * nfp + 1][1], addr);
            }
            uint32_t a[4][4];
#pragma unroll
            for (int mf = 0; mf < 4; mf++) {
                uint32_t addr = stg + ST_AHI + (uint32_t)(rA + mf * 16) * 128
                              + (uint32_t)(((ks * 2 + kaA) ^ sxA) * 16);
                ldsm_x4(a[mf][0], a[mf][1], a[mf][2], a[mf][3], addr);
            }
#pragma unroll
            for (int mf = 0; mf < 4; mf++)
#pragma unroll
                for (int nf = 0; nf < 4; nf++)
                    mma_bf16(c[mf][nf][0], c[mf][nf][1], c[mf][nf][2], c[mf][nf][3],
                             a[mf][0], a[mf][1], a[mf][2], a[mf][3],
                             b[nf][0], b[nf][1]);
            // lo half reuses B frags
#pragma unroll
            for (int mf = 0; mf < 4; mf++) {
                uint32_t addr = stg + ST_ALO + (uint32_t)(rA + mf * 16) * 128
                              + (uint32_t)(((ks * 2 + kaA) ^ sxA) * 16);
                ldsm_x4(a[mf][0], a[mf][1], a[mf][2], a[mf][3], addr);
            }
#pragma unroll
            for (int mf = 0; mf < 4; mf++)
#pragma unroll
                for (int nf = 0; nf < 4; nf++)
                    mma_bf16(c[mf][nf][0], c[mf][nf][1], c[mf][nf][2], c[mf][nf][3],
                             a[mf][0], a[mf][1], a[mf][2], a[mf][3],
                             b[nf][0], b[nf][1]);
        }

        __syncthreads();
        if (ck + 3 < NCHUNK) {
#pragma unroll
            for (int i = 0; i < 8; i++)
                cp_async16(stg + soff[i], gB + goff[i] + (ck + 3) * 128);
        }
        asm volatile("cp.async.commit_group;");
        stg_i++; if (stg_i == 3) stg_i = 0;
    }
    __syncthreads();

    // ---- epilogue: h = clip(C + b1) -> smem (f32) ---------------------------
    float* hsm = (float*)(smem + SM_H);
    const float* b1s = (const float*)(smem + SM_B1);
#pragma unroll
    for (int mf = 0; mf < 4; mf++) {
#pragma unroll
        for (int nf = 0; nf < 4; nf++) {
            const int row0 = warpM * 64 + mf * 16 + (lane >> 2);
            const int col  = warpN * 32 + nf * 8 + 2 * (lane & 3);
            const float bb0 = b1s[col], bb1 = b1s[col + 1];
            float v0 = fminf(fmaxf(c[mf][nf][0] + bb0, -1.f), 1.f);
            float v1 = fminf(fmaxf(c[mf][nf][1] + bb1, -1.f), 1.f);
            float v2 = fminf(fmaxf(c[mf][nf][2] + bb0, -1.f), 1.f);
            float v3 = fminf(fmaxf(c[mf][nf][3] + bb1, -1.f), 1.f);
            *(float2*)&hsm[row0 * H_STRIDE + col]       = make_float2(v0, v1);
            *(float2*)&hsm[(row0 + 8) * H_STRIDE + col] = make_float2(v2, v3);
        }
    }
    __syncthreads();

    // ---- layer 2: partial[r][0..9] over this CTA's 256 cols -----------------
    {
        const int r  = tid >> 2;         // 0..127
        const int tg = tid & 3;          // 4 threads per row, 64 cols each
        const float* w2s = (const float*)(smem + SM_W2);
        float acc[10];
#pragma unroll
        for (int o = 0; o < 10; o++) acc[o] = 0.f;
#pragma unroll 4
        for (int j = 0; j < 64; j++) {
            const int cc = tg * 64 + ((j + tg * 8) & 63);
            const float hv = hsm[r * H_STRIDE + cc];
#pragma unroll
            for (int o = 0; o < 10; o++)
                acc[o] += hv * w2s[o * 256 + cc];
        }
#pragma unroll
        for (int o = 0; o < 10; o++) {
            acc[o] += __shfl_xor_sync(0xffffffffu, acc[o], 1);
            acc[o] += __shfl_xor_sync(0xffffffffu, acc[o], 2);
        }
        const size_t base = ((size_t)blockIdx.y * BATCH + m0 + r) * 16;
        if (tg == 0)
            *(float4*)&g_part[base]     = make_float4(acc[0], acc[1], acc[2], acc[3]);
        else if (tg == 1)
            *(float4*)&g_part[base + 4] = make_float4(acc[4], acc[5], acc[6], acc[7]);
        else if (tg == 2)
            *(float4*)&g_part[base + 8] = make_float4(acc[8], acc[9], 0.f, 0.f);
    }
}

// ---------------- launch ------------------------------------------------------
extern "C" void kernel_launch(void* const* d_in, const int* in_sizes, int n_in,
                              void* d_out, int out_size) {
    const float* x  = (const float*)d_in[0];
    const float* W1 = (const float*)d_in[1];
    const float* b1 = (const float*)d_in[2];
    const float* W2 = (const float*)d_in[3];
    const float* b2 = (const float*)d_in[4];
    float* out = (float*)d_out;

    cudaFuncSetAttribute(mlp_kernel,
                         cudaFuncAttributeMaxDynamicSharedMemorySize, SMEM_TOTAL);

    prep_x<<<(BATCH * KP + 255) / 256, 256>>>(x);
    prep_w<<<(HID * KP + 255) / 256, 256>>>(W1);
    mlp_kernel<<<dim3(NT_M, NT_N), 512, SMEM_TOTAL>>>(b1, W2);
    reduce_out<<<(BATCH * OUT_F + 255) / 256, 256>>>(b2, out);
}